// round 11
// baseline (speedup 1.0000x reference)
#include <cuda_runtime.h>
#include <cstdint>

// out[B,10] = x[B,64] @ W[64,10], fp32, B = 2,097,152.
// R9: R7's const-port traffic (160 LDC.128 per 2 rows) saturated l1tex (84%).
// Fix: output-pair f32x2 accumulators + RPT=4 -> per k only 40B of W
// (2xLDC.128+1xLDC.64) amortized over 4 rows; x broadcast dup-movs go to the
// idle alu pipe. Stores stay direct STG.64 pairs (no reduction).

#define BATCH   2097152
#define IN_DIM  64
#define OUT_DIM 10
#define BLOCK   256
#define RPT     4
#define PF      2
#define NCHUNK  16                      // float4 chunks per 256B row
#define ROWS_PER_BLOCK (BLOCK * RPT)    // 1024

__device__ unsigned long long Wstage[IN_DIM * 6];     // staging (prep kernel)
__constant__ unsigned long long cW[IN_DIM * 6];       // cW[k*6+p]=(W[k][2p],W[k][2p+1]), p<5

__global__ void prep_kernel(const float* __restrict__ W) {
    int t = threadIdx.x;                 // 0..383
    if (t < IN_DIM * 6) {
        int k = t / 6, p = t % 6;
        float lo = 0.f, hi = 0.f;
        if (p < 5) {
            lo = W[k * OUT_DIM + 2 * p];
            hi = W[k * OUT_DIM + 2 * p + 1];
        }
        unsigned long long v;
        asm("mov.b64 %0, {%1, %2};" : "=l"(v) : "f"(lo), "f"(hi));
        Wstage[t] = v;
    }
}

__device__ __forceinline__ void ffma2(uint64_t& d, uint64_t a, uint64_t b) {
    asm volatile("fma.rn.f32x2 %0, %1, %2, %0;" : "+l"(d) : "l"(a), "l"(b));
}

__device__ __forceinline__ uint64_t dup2(float v) {
    uint64_t d;
    asm("mov.b64 %0, {%1, %1};" : "=l"(d) : "f"(v));
    return d;
}

__global__ void __launch_bounds__(BLOCK) neat_matmul_kernel(
    const float* __restrict__ x,
    float* __restrict__ out)
{
    const int tid = threadIdx.x;
    const size_t base = (size_t)blockIdx.x * ROWS_PER_BLOCK + tid;

    // Block-strided rows -> every warp LDG.128 fully coalesced.
    const float4* __restrict__ xb =
        reinterpret_cast<const float4*>(x) + base * NCHUNK;

    // acc[r][p] = (out[2p], out[2p+1]) for row r.
    uint64_t acc[RPT][5];
#pragma unroll
    for (int r = 0; r < RPT; ++r)
#pragma unroll
        for (int p = 0; p < 5; ++p) acc[r][p] = 0ull;

    // PF=2 chunk double-buffer: 8 LDG.128 in flight per thread continuously.
    float4 buf[PF][RPT];
#pragma unroll
    for (int s = 0; s < PF; ++s)
#pragma unroll
        for (int r = 0; r < RPT; ++r)
            buf[s][r] = __ldcs(xb + (size_t)r * BLOCK * NCHUNK + s);

#pragma unroll
    for (int c = 0; c < NCHUNK; ++c) {
        float4 xv[RPT];
#pragma unroll
        for (int r = 0; r < RPT; ++r) xv[r] = buf[c % PF][r];

        if (c + PF < NCHUNK) {
#pragma unroll
            for (int r = 0; r < RPT; ++r)
                buf[c % PF][r] =
                    __ldcs(xb + (size_t)r * BLOCK * NCHUNK + c + PF);
        }

#pragma unroll
        for (int q = 0; q < 4; ++q) {
            const int k = 4 * c + q;
            // 40B of W for this k: 2 LDC.128 + 1 LDC.64, shared by 4 rows.
            const ulonglong2 w01 =
                *reinterpret_cast<const ulonglong2*>(&cW[k * 6]);
            const ulonglong2 w23 =
                *reinterpret_cast<const ulonglong2*>(&cW[k * 6 + 2]);
            const uint64_t w4 = cW[k * 6 + 4];
#pragma unroll
            for (int r = 0; r < RPT; ++r) {
                const float xk = (q == 0) ? xv[r].x :
                                 (q == 1) ? xv[r].y :
                                 (q == 2) ? xv[r].z : xv[r].w;
                const uint64_t xx = dup2(xk);     // alu pipe, not l1tex
                ffma2(acc[r][0], xx, w01.x);
                ffma2(acc[r][1], xx, w01.y);
                ffma2(acc[r][2], xx, w23.x);
                ffma2(acc[r][3], xx, w23.y);
                ffma2(acc[r][4], xx, w4);
            }
        }
    }

    // acc pairs are (out[2p], out[2p+1]) -> 5 x STG.64 per row, no reduce.
#pragma unroll
    for (int r = 0; r < RPT; ++r) {
        unsigned long long* __restrict__ o =
            reinterpret_cast<unsigned long long*>(
                out + (base + (size_t)r * BLOCK) * OUT_DIM);
#pragma unroll
        for (int p = 0; p < 5; ++p)
            __stcs(o + p, (unsigned long long)acc[r][p]);
    }
}

extern "C" void kernel_launch(void* const* d_in, const int* in_sizes, int n_in,
                              void* d_out, int out_size) {
    const float* x = (const float*)d_in[0];  // [BATCH, 64]
    const float* W = (const float*)d_in[1];  // [64, 10] row-major
    float* out = (float*)d_out;              // [BATCH, 10]

    // 1) pack W -> (pairs, padded rows of 6 u64) in device staging
    prep_kernel<<<1, IN_DIM * 6>>>(W);

    // 2) staging -> constant bank (graph-capturable D2D copy)
    void* wsp = nullptr;
    cudaGetSymbolAddress(&wsp, Wstage);
    cudaMemcpyToSymbolAsync(cW, wsp, IN_DIM * 6 * sizeof(unsigned long long), 0,
                            cudaMemcpyDeviceToDevice, 0);

    // 3) main streaming kernel
    const int grid = BATCH / ROWS_PER_BLOCK;   // 2048, exact
    neat_matmul_kernel<<<grid, BLOCK>>>(x, out);
}

// round 15
// speedup vs baseline: 1.4017x; 1.4017x over previous
#include <cuda_runtime.h>
#include <cstdint>

// out[B,10] = x[B,64] @ W[64,10], fp32, B = 2,097,152.
// R11: the wall was uncoalesced LDG (lane-per-row => nL=32 lines/LDG => 16
// l1tex wavefronts/row, ~130us floor). Fix: per-warp private smem double
// buffer filled by fully-coalesced cp.async (4 wf/instr), consumed lane=row
// with 272B row stride (bank quad (l+c)%8 => conflict-free LDS.128, chunk
// index warp-uniform => W stays on the uniform const port). No block barriers:
// each warp's cp.async ring is private (commit/wait are per-thread state).

#define BATCH     2097152
#define IN_DIM    64
#define OUT_DIM   10
#define BLOCK     256
#define WARPS     8
#define TILE_ROWS 32
#define TPW       4                            // tiles per warp
#define ROW_STRIDE 272                         // 256B data + 16B pad (odd*16)
#define BUF_BYTES  (TILE_ROWS * ROW_STRIDE)    // 8704
#define WARP_SMEM  (2 * BUF_BYTES)             // 17408 (double buffer)
#define SMEM_TOTAL (WARPS * WARP_SMEM)         // 139264 -> 1 CTA/SM
#define ROWS_PER_BLOCK (WARPS * TPW * TILE_ROWS)  // 1024

__device__ unsigned long long Wstage[IN_DIM * 6];
__constant__ unsigned long long cW[IN_DIM * 6];   // cW[k*6+p]=(W[k][2p],W[k][2p+1]), p<5

__global__ void prep_kernel(const float* __restrict__ W) {
    int t = threadIdx.x;                 // 0..383
    if (t < IN_DIM * 6) {
        int k = t / 6, p = t % 6;
        float lo = 0.f, hi = 0.f;
        if (p < 5) {
            lo = W[k * OUT_DIM + 2 * p];
            hi = W[k * OUT_DIM + 2 * p + 1];
        }
        unsigned long long v;
        asm("mov.b64 %0, {%1, %2};" : "=l"(v) : "f"(lo), "f"(hi));
        Wstage[t] = v;
    }
}

__device__ __forceinline__ void ffma2(uint64_t& d, uint64_t a, uint64_t b) {
    asm volatile("fma.rn.f32x2 %0, %1, %2, %0;" : "+l"(d) : "l"(a), "l"(b));
}

__device__ __forceinline__ uint64_t dup2(float v) {
    uint64_t d;
    asm("mov.b64 %0, {%1, %1};" : "=l"(d) : "f"(v));
    return d;
}

__global__ void __launch_bounds__(BLOCK) neat_matmul_kernel(
    const float* __restrict__ x,
    float* __restrict__ out)
{
    extern __shared__ __align__(128) unsigned char smem[];
    const int tid  = threadIdx.x;
    const int warp = tid >> 5;
    const int lane = tid & 31;

    const unsigned sbase =
        (unsigned)__cvta_generic_to_shared(smem) + warp * WARP_SMEM;
    const size_t warpRow0 = (size_t)blockIdx.x * ROWS_PER_BLOCK
                          + (size_t)warp * (TPW * TILE_ROWS);
    const char* xw = reinterpret_cast<const char*>(x) + warpRow0 * (IN_DIM * 4);

    // Issue one 32-row tile (8KB) into buffer b. Per instr i: lanes 0-15 cover
    // row 2i fully (256B), lanes 16-31 row 2i+1 -> 512B contiguous = 4 lines.
    auto issue = [&](int t, int b) {
        const char* src0 = xw + (size_t)t * (TILE_ROWS * 256);
        unsigned dst0 = sbase + b * BUF_BYTES;
        int r = lane >> 4;             // 0 or 1
        int c = lane & 15;
#pragma unroll
        for (int i = 0; i < 16; ++i) {
            const char* src = src0 + (2 * i + r) * 256 + c * 16;
            unsigned dst = dst0 + (2 * i + r) * ROW_STRIDE + c * 16;
            asm volatile("cp.async.cg.shared.global [%0], [%1], 16;"
                         :: "r"(dst), "l"(src) : "memory");
        }
        asm volatile("cp.async.commit_group;" ::: "memory");
    };

    issue(0, 0);                       // prime
    if (TPW > 1) issue(1, 1);

    for (int t = 0; t < TPW; ++t) {
        // Drain: after this wait, tile t is resident. One extra group
        // (tile t+1) may remain outstanding.
        if (t + 1 < TPW)
            asm volatile("cp.async.wait_group 1;" ::: "memory");
        else
            asm volatile("cp.async.wait_group 0;" ::: "memory");
        __syncwarp();

        const unsigned rowb = sbase + (t & 1) * BUF_BYTES + lane * ROW_STRIDE;

        uint64_t acc[5];
#pragma unroll
        for (int p = 0; p < 5; ++p) acc[p] = 0ull;

#pragma unroll
        for (int c = 0; c < 16; ++c) {
            // Conflict-free LDS.128: bank quad = (lane + c) mod 8, distinct
            // within each 8-lane phase group.
            float4 xv;
            asm volatile("ld.shared.v4.f32 {%0,%1,%2,%3}, [%4];"
                         : "=f"(xv.x), "=f"(xv.y), "=f"(xv.z), "=f"(xv.w)
                         : "r"(rowb + c * 16));
#pragma unroll
            for (int q = 0; q < 4; ++q) {
                const int k = 4 * c + q;   // warp-uniform -> ULDC const port
                const ulonglong2 w01 =
                    *reinterpret_cast<const ulonglong2*>(&cW[k * 6]);
                const ulonglong2 w23 =
                    *reinterpret_cast<const ulonglong2*>(&cW[k * 6 + 2]);
                const uint64_t w4 = cW[k * 6 + 4];
                const float xk = (q == 0) ? xv.x : (q == 1) ? xv.y :
                                 (q == 2) ? xv.z : xv.w;
                const uint64_t xx = dup2(xk);
                ffma2(acc[0], xx, w01.x);
                ffma2(acc[1], xx, w01.y);
                ffma2(acc[2], xx, w23.x);
                ffma2(acc[3], xx, w23.y);
                ffma2(acc[4], xx, w4);
            }
        }

        // All lanes finished reading buffer (t&1) -> safe to refill with t+2.
        __syncwarp();
        if (t + 2 < TPW) issue(t + 2, t & 1);

        // acc[p] = (out[2p], out[2p+1]) -> 5 x STG.64 streaming.
        const size_t row = warpRow0 + (size_t)t * TILE_ROWS + lane;
        unsigned long long* __restrict__ o =
            reinterpret_cast<unsigned long long*>(out + row * OUT_DIM);
#pragma unroll
        for (int p = 0; p < 5; ++p)
            __stcs(o + p, (unsigned long long)acc[p]);
    }
}

extern "C" void kernel_launch(void* const* d_in, const int* in_sizes, int n_in,
                              void* d_out, int out_size) {
    const float* x = (const float*)d_in[0];  // [BATCH, 64]
    const float* W = (const float*)d_in[1];  // [64, 10] row-major
    float* out = (float*)d_out;              // [BATCH, 10]

    prep_kernel<<<1, IN_DIM * 6>>>(W);

    void* wsp = nullptr;
    cudaGetSymbolAddress(&wsp, Wstage);
    cudaMemcpyToSymbolAsync(cW, wsp, IN_DIM * 6 * sizeof(unsigned long long), 0,
                            cudaMemcpyDeviceToDevice, 0);

    static int configured = 0;
    if (!configured) {
        cudaFuncSetAttribute(neat_matmul_kernel,
                             cudaFuncAttributeMaxDynamicSharedMemorySize,
                             SMEM_TOTAL);
        configured = 1;
    }

    const int grid = BATCH / ROWS_PER_BLOCK;   // 2048, exact
    neat_matmul_kernel<<<grid, BLOCK, SMEM_TOTAL>>>(x, out);
}